// round 13
// baseline (speedup 1.0000x reference)
#include <cuda_runtime.h>
#include <cuda_bf16.h>
#include <math.h>
#include <stdint.h>

#define BB 8
#define TT 4096
#define DD 512
#define VV 50257
#define NSLOTS 256
#define KWIN 8
#define NTOK (BB*TT)          // 32768

// ---------------- scratch (device globals; no allocation) ----------------
__device__ __nv_bfloat16 g_h0h[(size_t)NTOK*DD];
__device__ __nv_bfloat16 g_h0l[(size_t)NTOK*DD];
__device__ __nv_bfloat16 g_a1h[(size_t)NTOK*2*DD];
__device__ __nv_bfloat16 g_a1l[(size_t)NTOK*2*DD];
__device__ float g_ff[(size_t)NTOK*DD];
__device__ float g_h [(size_t)NTOK*DD];
__device__ __nv_bfloat16 g_w1th[(size_t)2*DD*DD];
__device__ __nv_bfloat16 g_w1tl[(size_t)2*DD*DD];
__device__ __nv_bfloat16 g_w2th[(size_t)DD*2*DD];
__device__ __nv_bfloat16 g_w2tl[(size_t)DD*2*DD];
__device__ float g_u[NTOK];
__device__ float g_v[NTOK];
__device__ float g_gate[NTOK];
__device__ int   g_top[BB*NSLOTS];
__device__ float g_q[BB*DD];
__device__ float g_ctx[BB*DD];

// ======================= helpers =======================
__device__ __forceinline__ uint32_t smem_to_u32(const void* p) {
    uint32_t a;
    asm("{ .reg .u64 t; cvta.to.shared.u64 t, %1; cvt.u32.u64 %0, t; }" : "=r"(a) : "l"(p));
    return a;
}
__device__ __forceinline__ void bsplit(float x, __nv_bfloat16& h, __nv_bfloat16& l) {
    h = __float2bfloat16_rn(x);
    l = __float2bfloat16_rn(x - __bfloat162float(h));
}
__device__ __forceinline__ void ldm_x4(uint32_t& r0, uint32_t& r1, uint32_t& r2, uint32_t& r3,
                                       uint32_t addr) {
    asm volatile("ldmatrix.sync.aligned.m8n8.x4.shared.b16 {%0,%1,%2,%3}, [%4];"
        : "=r"(r0), "=r"(r1), "=r"(r2), "=r"(r3) : "r"(addr));
}
__device__ __forceinline__ void mma_bf16(float* c, const uint32_t* a, const uint32_t* b) {
    asm volatile("mma.sync.aligned.m16n8k16.row.col.f32.bf16.bf16.f32 "
        "{%0,%1,%2,%3}, {%4,%5,%6,%7}, {%8,%9}, {%0,%1,%2,%3};"
        : "+f"(c[0]), "+f"(c[1]), "+f"(c[2]), "+f"(c[3])
        : "r"(a[0]), "r"(a[1]), "r"(a[2]), "r"(a[3]), "r"(b[0]), "r"(b[1]));
}
__device__ __forceinline__ void cpasync16(uint32_t s, const void* g) {
    asm volatile("cp.async.cg.shared.global [%0], [%1], 16;" :: "r"(s), "l"(g) : "memory");
}
__device__ __forceinline__ void cp_commit() {
    asm volatile("cp.async.commit_group;" ::: "memory");
}
template<int N>
__device__ __forceinline__ void cp_wait() {
    asm volatile("cp.async.wait_group %0;" :: "n"(N) : "memory");
}

// ---------------- weight transpose + bf16 split ----------------
__global__ void transpose_convert_kernel(const float* __restrict__ src,
                                         __nv_bfloat16* __restrict__ dh,
                                         __nv_bfloat16* __restrict__ dl,
                                         int R, int C) {
    __shared__ float t[32][33];
    int bx = blockIdx.x * 32, by = blockIdx.y * 32;
    int x = bx + threadIdx.x;
    #pragma unroll
    for (int j = 0; j < 32; j += 8) {
        int y = by + threadIdx.y + j;
        t[threadIdx.y + j][threadIdx.x] = src[(size_t)y * C + x];
    }
    __syncthreads();
    int xo = by + threadIdx.x;
    #pragma unroll
    for (int j = 0; j < 32; j += 8) {
        int yo = bx + threadIdx.y + j;
        float v = t[threadIdx.x][threadIdx.y + j];
        __nv_bfloat16 h, l; bsplit(v, h, l);
        dh[(size_t)yo * R + xo] = h;
        dl[(size_t)yo * R + xo] = l;
    }
}

// ---------------- embedding gather + bf16 split ----------------
__global__ void gather_kernel(const int* __restrict__ seq,
                              const float* __restrict__ embed) {
    long i = (long)blockIdx.x * blockDim.x + threadIdx.x;
    long total = (long)NTOK * (DD/4);
    if (i >= total) return;
    int tokpos = (int)(i >> 7);
    int dc     = (int)(i & 127);
    int tok = seq[tokpos];
    float4 e = ((const float4*)embed)[(long)tok * 128 + dc];
    __nv_bfloat16 hx, lx, hy, ly, hz, lz, hw, lw;
    bsplit(e.x, hx, lx); bsplit(e.y, hy, ly);
    bsplit(e.z, hz, lz); bsplit(e.w, hw, lw);
    __nv_bfloat162* ph = (__nv_bfloat162*)g_h0h + i * 2;
    __nv_bfloat162* pl = (__nv_bfloat162*)g_h0l + i * 2;
    ph[0] = __nv_bfloat162{hx, hy}; ph[1] = __nv_bfloat162{hz, hw};
    pl[0] = __nv_bfloat162{lx, ly}; pl[1] = __nv_bfloat162{lz, lw};
}

// ============== mma.sync bf16 3-pass split GEMM, K-chunk 32 ==============
// CTA 128x128, 8 warps (2m x 4n), warp tile 64x32, K-chunk 32 (2 k16 slices),
// cp.async 2-stage double buffer, per-slice pass order hh -> lh -> hl.
// tile: 128 rows * 80B pitch (64B data = 2 k16 slices + 16B pad) = 10240 B
// pitch 80B is ldmatrix bank-conflict-free: (20*r) mod 32 spans disjoint, r=0..7
#define STILE 10240
#define TB(arr, buf) ((uint32_t)(((buf) * 4 + (arr)) * STILE))
#define GEMM_SMEM (8 * STILE)   // 81920

template<int EPI>
__global__ void __launch_bounds__(256, 2)
mma_gemm_kernel(const __nv_bfloat16* __restrict__ Ah, const __nv_bfloat16* __restrict__ Al,
                const __nv_bfloat16* __restrict__ Bh, const __nv_bfloat16* __restrict__ Bl,
                const float* __restrict__ bias,
                float* __restrict__ Cf,
                __nv_bfloat16* __restrict__ Ch, __nv_bfloat16* __restrict__ Cl,
                int M, int N, int K) {
    extern __shared__ char smem[];
    uint32_t sb = smem_to_u32(smem);
    int tid = threadIdx.x;
    int lane = tid & 31, wid = tid >> 5;
    int wm = wid >> 2, wn = wid & 3;            // 2 x 4 warp grid, warp tile 64x32
    int bx = blockIdx.x, by = blockIdx.y;

    // global->smem: 256 threads, two 16B transfers per array per chunk
    int grow = tid >> 1;                        // row 0..127
    int gp = (tid & 1) * 2;                     // 16B part 0/2 (thread does gp, gp+1)
    const __nv_bfloat16* pAh = Ah + (size_t)(by * 128 + grow) * K + gp * 8;
    const __nv_bfloat16* pAl = Al + (size_t)(by * 128 + grow) * K + gp * 8;
    const __nv_bfloat16* pBh = Bh + (size_t)(bx * 128 + grow) * K + gp * 8;
    const __nv_bfloat16* pBl = Bl + (size_t)(bx * 128 + grow) * K + gp * 8;
    uint32_t sdst = (uint32_t)(grow * 80 + gp * 16);

    float acc[4][4][4];
    #pragma unroll
    for (int i = 0; i < 4; i++)
        #pragma unroll
        for (int j = 0; j < 4; j++)
            #pragma unroll
            for (int r = 0; r < 4; r++) acc[i][j][r] = 0.f;

    uint32_t a_off = (uint32_t)((wm * 64 + (lane & 15)) * 80 + (lane >> 4) * 16);
    uint32_t b_off = (uint32_t)((wn * 32 + (lane & 7) + ((lane >> 4) << 3)) * 80
                                + ((lane >> 3) & 1) * 16);

    int nk = K >> 5;                            // chunks of 32

    // prologue: chunk 0 -> buf 0
    {
        cpasync16(sb + TB(0,0) + sdst,      pAh);
        cpasync16(sb + TB(0,0) + sdst + 16, pAh + 8);
        cpasync16(sb + TB(1,0) + sdst,      pAl);
        cpasync16(sb + TB(1,0) + sdst + 16, pAl + 8);
        cpasync16(sb + TB(2,0) + sdst,      pBh);
        cpasync16(sb + TB(2,0) + sdst + 16, pBh + 8);
        cpasync16(sb + TB(3,0) + sdst,      pBl);
        cpasync16(sb + TB(3,0) + sdst + 16, pBl + 8);
        cp_commit();
    }

    for (int c = 0; c < nk; c++) {
        int buf = c & 1;
        if (c + 1 < nk) {
            int nb = buf ^ 1;
            int k0 = (c + 1) * 32;
            cpasync16(sb + TB(0,nb) + sdst,      pAh + k0);
            cpasync16(sb + TB(0,nb) + sdst + 16, pAh + k0 + 8);
            cpasync16(sb + TB(1,nb) + sdst,      pAl + k0);
            cpasync16(sb + TB(1,nb) + sdst + 16, pAl + k0 + 8);
            cpasync16(sb + TB(2,nb) + sdst,      pBh + k0);
            cpasync16(sb + TB(2,nb) + sdst + 16, pBh + k0 + 8);
            cpasync16(sb + TB(3,nb) + sdst,      pBl + k0);
            cpasync16(sb + TB(3,nb) + sdst + 16, pBl + k0 + 8);
            cp_commit();
            cp_wait<1>();
        } else {
            cp_wait<0>();
        }
        __syncthreads();

        uint32_t sAh = sb + TB(0, buf), sAl = sb + TB(1, buf);
        uint32_t sBh = sb + TB(2, buf), sBl = sb + TB(3, buf);

        #pragma unroll
        for (int s = 0; s < 2; s++) {           // two k16 slices per chunk
            uint32_t so = (uint32_t)(s * 32);   // byte offset of slice within row
            uint32_t ah[4][4], al[4][4], bb[4][2], bb2[4][2];
            #pragma unroll
            for (int mt = 0; mt < 4; mt++)
                ldm_x4(ah[mt][0], ah[mt][1], ah[mt][2], ah[mt][3],
                       sAh + a_off + so + mt * 1280);
            #pragma unroll
            for (int p = 0; p < 2; p++)
                ldm_x4(bb[2*p][0], bb[2*p][1], bb[2*p+1][0], bb[2*p+1][1],
                       sBh + b_off + so + p * 1280);
            // pass hh
            #pragma unroll
            for (int mt = 0; mt < 4; mt++)
                #pragma unroll
                for (int nt = 0; nt < 4; nt++) mma_bf16(acc[mt][nt], ah[mt], bb[nt]);
            // pass lh (B_hi resident)
            #pragma unroll
            for (int mt = 0; mt < 4; mt++)
                ldm_x4(al[mt][0], al[mt][1], al[mt][2], al[mt][3],
                       sAl + a_off + so + mt * 1280);
            #pragma unroll
            for (int mt = 0; mt < 4; mt++)
                #pragma unroll
                for (int nt = 0; nt < 4; nt++) mma_bf16(acc[mt][nt], al[mt], bb[nt]);
            // pass hl (A_hi resident; separate bb2 regs avoid WAR on bb)
            #pragma unroll
            for (int p = 0; p < 2; p++)
                ldm_x4(bb2[2*p][0], bb2[2*p][1], bb2[2*p+1][0], bb2[2*p+1][1],
                       sBl + b_off + so + p * 1280);
            #pragma unroll
            for (int mt = 0; mt < 4; mt++)
                #pragma unroll
                for (int nt = 0; nt < 4; nt++) mma_bf16(acc[mt][nt], ah[mt], bb2[nt]);
        }

        __syncthreads();
    }

    // ---- epilogue ----
    int m_base = by * 128 + wm * 64;
    int n_base = bx * 128 + wn * 32;
    #pragma unroll
    for (int mt = 0; mt < 4; mt++) {
        #pragma unroll
        for (int nt = 0; nt < 4; nt++) {
            int n0 = n_base + nt * 8 + (lane & 3) * 2;
            float bs0 = bias[n0], bs1 = bias[n0 + 1];
            #pragma unroll
            for (int half = 0; half < 2; half++) {
                int m = m_base + mt * 16 + (lane >> 2) + half * 8;
                float v0 = acc[mt][nt][half * 2 + 0] + bs0;
                float v1 = acc[mt][nt][half * 2 + 1] + bs1;
                if (EPI) {
                    v0 = fmaxf(v0, 0.f); v1 = fmaxf(v1, 0.f);
                    __nv_bfloat16 h0b, l0b, h1b, l1b;
                    bsplit(v0, h0b, l0b); bsplit(v1, h1b, l1b);
                    *(__nv_bfloat162*)(Ch + (size_t)m * N + n0) = __nv_bfloat162{h0b, h1b};
                    *(__nv_bfloat162*)(Cl + (size_t)m * N + n0) = __nv_bfloat162{l0b, l1b};
                } else {
                    *(float2*)(Cf + (size_t)m * N + n0) = float2{v0, v1};
                }
            }
        }
    }
}

// ---------------- block reduce helper ----------------
__device__ __forceinline__ float block_reduce_sum(float v, float* red) {
    int tid = threadIdx.x;
    #pragma unroll
    for (int o = 16; o > 0; o >>= 1) v += __shfl_down_sync(0xffffffffu, v, o);
    if ((tid & 31) == 0) red[tid >> 5] = v;
    __syncthreads();
    int nw = blockDim.x >> 5;
    if (tid < 32) {
        float x = (tid < nw) ? red[tid] : 0.f;
        #pragma unroll
        for (int o = 16; o > 0; o >>= 1) x += __shfl_down_sync(0xffffffffu, x, o);
        if (tid == 0) red[0] = x;
    }
    __syncthreads();
    float r = red[0];
    __syncthreads();
    return r;
}

// ---------------- fused layernorm(h0 + ff) + gate dots ----------------
__global__ void __launch_bounds__(256)
ln_kernel(const float* __restrict__ g, const float* __restrict__ b,
          const float* __restrict__ gW) {
    __shared__ float red[32];
    int row = blockIdx.x;
    int tid = threadIdx.x;
    long base = (long)row * DD;
    float x1 = __bfloat162float(g_h0h[base + tid]) + __bfloat162float(g_h0l[base + tid])
             + g_ff[base + tid];
    float x2 = __bfloat162float(g_h0h[base + tid + 256]) + __bfloat162float(g_h0l[base + tid + 256])
             + g_ff[base + tid + 256];
    float mean = block_reduce_sum(x1 + x2, red) * (1.f / DD);
    float d1 = x1 - mean, d2 = x2 - mean;
    float var = block_reduce_sum(d1*d1 + d2*d2, red) * (1.f / DD);
    float rstd = rsqrtf(var + 1e-5f);
    float h1 = d1 * rstd * g[tid]       + b[tid];
    float h2 = d2 * rstd * g[tid + 256] + b[tid + 256];
    g_h[base + tid]       = h1;
    g_h[base + tid + 256] = h2;
    float su = h1 * gW[tid]      + h2 * gW[tid + 256];
    float sv = h1 * gW[DD + tid] + h2 * gW[DD + tid + 256];
    su = block_reduce_sum(su, red);
    sv = block_reduce_sum(sv, red);
    if (tid == 0) { g_u[row] = su; g_v[row] = sv; }
}

// ---------------- gate = sigmoid(u + windowed-mean(v) + gb) ----------------
__global__ void gatecomb_kernel(const float* __restrict__ gb) {
    int i = blockIdx.x * blockDim.x + threadIdx.x;
    if (i >= NTOK) return;
    int t = i % TT;
    int bstart = i - t;
    int s = min(t + 1, TT);
    int e = min(t + 1 + KWIN, TT);
    int cnt = e - s;
    float fsum = 0.f;
    for (int j = s; j < e; j++) fsum += g_v[bstart + j];
    float fut = (cnt > 0) ? fsum / (float)cnt : 0.f;
    float logit = g_u[i] + fut + gb[0];
    g_gate[i] = 1.f / (1.f + expf(-logit));
}

// ---------------- top-256 per batch via 4-pass radix select ----------------
__global__ void __launch_bounds__(256)
topk_kernel() {
    __shared__ uint32_t keys[TT];        // 16 KB
    __shared__ int hist[256];
    __shared__ int wsg[8], wse[8];
    __shared__ uint32_t sh_prefix;
    __shared__ int sh_need, sh_gbase, sh_ebase;
    int b = blockIdx.x, tid = threadIdx.x;
    int lane = tid & 31, wid = tid >> 5;

    for (int i = tid; i < TT; i += 256) {
        uint32_t u = __float_as_uint(g_gate[b * TT + i]);
        u = (u & 0x80000000u) ? ~u : (u | 0x80000000u);
        keys[i] = u;
    }
    if (tid == 0) { sh_prefix = 0; sh_need = NSLOTS; sh_gbase = 0; sh_ebase = 0; }
    __syncthreads();

    for (int p = 3; p >= 0; p--) {
        hist[tid] = 0;
        __syncthreads();
        uint32_t pmask = (p == 3) ? 0u : (0xFFFFFFFFu << ((p + 1) * 8));
        uint32_t prefix = sh_prefix;
        int shift = p * 8;
        for (int i = tid; i < TT; i += 256) {
            uint32_t k = keys[i];
            if ((k & pmask) == prefix)
                atomicAdd(&hist[(k >> shift) & 0xFF], 1);
        }
        __syncthreads();
        if (tid == 0) {
            int need = sh_need, acc = 0, t = 255;
            for (; t > 0; t--) {
                if (acc + hist[t] >= need) break;
                acc += hist[t];
            }
            sh_need = need - acc;
            sh_prefix = prefix | ((uint32_t)t << shift);
        }
        __syncthreads();
    }
    uint32_t T = sh_prefix;
    int need = sh_need;

    for (int base = 0; base < TT; base += 256) {
        uint32_t k = keys[base + tid];
        bool sg = (k > T);
        bool se = (k == T);
        unsigned bg = __ballot_sync(0xffffffffu, sg);
        unsigned be = __ballot_sync(0xffffffffu, se);
        if (lane == 0) { wsg[wid] = __popc(bg); wse[wid] = __popc(be); }
        __syncthreads();
        int wog = 0, woe = 0;
        for (int w = 0; w < wid; w++) { wog += wsg[w]; woe += wse[w]; }
        unsigned lmask = (1u << lane) - 1;
        if (sg) {
            int rg = sh_gbase + wog + __popc(bg & lmask);
            g_top[b * NSLOTS + rg] = base + tid;
        }
        if (se) {
            int re = sh_ebase + woe + __popc(be & lmask);
            if (re < need)
                g_top[b * NSLOTS + (NSLOTS - need) + re] = base + tid;
        }
        __syncthreads();
        if (tid == 0) {
            int tg = 0, te = 0;
            for (int w = 0; w < 8; w++) { tg += wsg[w]; te += wse[w]; }
            sh_gbase += tg; sh_ebase += te;
        }
        __syncthreads();
    }
}

// ---------------- q = h[:, -1, :] @ q_W + q_b ----------------
__global__ void __launch_bounds__(256)
q_kernel(const float* __restrict__ qW, const float* __restrict__ qb) {
    __shared__ float hl[DD];
    int b = blockIdx.x;
    int tid = threadIdx.x;
    long base = ((long)b * TT + (TT - 1)) * DD;
    for (int d = tid; d < DD; d += 256) hl[d] = g_h[base + d];
    __syncthreads();
    for (int j = tid; j < DD; j += 256) {
        float s = qb[j];
        for (int d = 0; d < DD; d++) s += hl[d] * qW[(long)d * DD + j];
        g_q[b * DD + j] = s;
    }
}

// ---------------- scores -> softmax -> ctx ----------------
__global__ void __launch_bounds__(256)
attn_kernel() {
    __shared__ float qs[DD];
    __shared__ float sc[NSLOTS];
    __shared__ int   rows[NSLOTS];
    __shared__ float red[32];
    int b = blockIdx.x;
    int tid = threadIdx.x;
    int wid = tid >> 5, lane = tid & 31;
    for (int d = tid; d < DD; d += 256) qs[d] = g_q[b * DD + d];
    for (int m = tid; m < NSLOTS; m += 256) rows[m] = b * TT + g_top[b * NSLOTS + m];
    __syncthreads();
    for (int m = wid; m < NSLOTS; m += 8) {
        long base = (long)rows[m] * DD;
        float s = 0.f;
        for (int d = lane; d < DD; d += 32) s += g_h[base + d] * qs[d];
        #pragma unroll
        for (int o = 16; o > 0; o >>= 1) s += __shfl_down_sync(0xffffffffu, s, o);
        if (lane == 0) sc[m] = s;
    }
    __syncthreads();
    float v = (tid < NSLOTS) ? sc[tid] : -1e30f;
    float vm = v;
    #pragma unroll
    for (int o = 16; o > 0; o >>= 1) vm = fmaxf(vm, __shfl_down_sync(0xffffffffu, vm, o));
    if ((tid & 31) == 0) red[tid >> 5] = vm;
    __syncthreads();
    if (tid < 32) {
        float x = (tid < 8) ? red[tid] : -1e30f;
        #pragma unroll
        for (int o = 16; o > 0; o >>= 1) x = fmaxf(x, __shfl_down_sync(0xffffffffu, x, o));
        if (tid == 0) red[0] = x;
    }
    __syncthreads();
    float mx = red[0];
    __syncthreads();
    float e = (tid < NSLOTS) ? expf(v - mx) : 0.f;
    float tot = block_reduce_sum(e, red);
    if (tid < NSLOTS) sc[tid] = e / tot;
    __syncthreads();
    for (int d = tid; d < DD; d += 256) {
        float s = 0.f;
        for (int m = 0; m < NSLOTS; m++)
            s += sc[m] * g_h[(long)rows[m] * DD + d];
        g_ctx[b * DD + d] = s;
    }
}

// ---------------- out = ctx @ out_W + out_b ----------------
__global__ void __launch_bounds__(256)
out_kernel(const float* __restrict__ oW, const float* __restrict__ ob,
           float* __restrict__ out) {
    __shared__ float cs[BB * DD];
    int tid = threadIdx.x;
    for (int i = tid; i < BB * DD; i += 256) cs[i] = g_ctx[i];
    __syncthreads();
    int v = blockIdx.x * 256 + tid;
    if (v >= VV) return;
    float acc[BB];
    #pragma unroll
    for (int b = 0; b < BB; b++) acc[b] = 0.f;
    for (int d = 0; d < DD; d++) {
        float w = oW[(long)d * VV + v];
        #pragma unroll
        for (int b = 0; b < BB; b++) acc[b] += cs[b * DD + d] * w;
    }
    float bias = ob[v];
    #pragma unroll
    for (int b = 0; b < BB; b++) out[(long)b * VV + v] = acc[b] + bias;
}

// ---------------- launch ----------------
extern "C" void kernel_launch(void* const* d_in, const int* in_sizes, int n_in,
                              void* d_out, int out_size) {
    const int*   seq   = (const int*)  d_in[0];
    const float* embed = (const float*)d_in[1];
    const float* W1    = (const float*)d_in[2];
    const float* b1    = (const float*)d_in[3];
    const float* W2    = (const float*)d_in[4];
    const float* b2    = (const float*)d_in[5];
    const float* ln_g  = (const float*)d_in[6];
    const float* ln_b  = (const float*)d_in[7];
    const float* gW    = (const float*)d_in[8];
    const float* gb    = (const float*)d_in[9];
    const float* qW    = (const float*)d_in[10];
    const float* qb    = (const float*)d_in[11];
    const float* oW    = (const float*)d_in[12];
    const float* ob    = (const float*)d_in[13];
    float* out = (float*)d_out;

    __nv_bfloat16 *h0h, *h0l, *a1h, *a1l, *w1th, *w1tl, *w2th, *w2tl;
    float *ff;
    cudaGetSymbolAddress((void**)&h0h,  g_h0h);
    cudaGetSymbolAddress((void**)&h0l,  g_h0l);
    cudaGetSymbolAddress((void**)&a1h,  g_a1h);
    cudaGetSymbolAddress((void**)&a1l,  g_a1l);
    cudaGetSymbolAddress((void**)&w1th, g_w1th);
    cudaGetSymbolAddress((void**)&w1tl, g_w1tl);
    cudaGetSymbolAddress((void**)&w2th, g_w2th);
    cudaGetSymbolAddress((void**)&w2tl, g_w2tl);
    cudaGetSymbolAddress((void**)&ff,   g_ff);

    cudaFuncSetAttribute(mma_gemm_kernel<1>,
                         cudaFuncAttributeMaxDynamicSharedMemorySize, GEMM_SMEM);
    cudaFuncSetAttribute(mma_gemm_kernel<0>,
                         cudaFuncAttributeMaxDynamicSharedMemorySize, GEMM_SMEM);

    // 0. weight transpose + split
    transpose_convert_kernel<<<dim3(2*DD/32, DD/32), dim3(32, 8)>>>(W1, w1th, w1tl, DD, 2*DD);
    transpose_convert_kernel<<<dim3(DD/32, 2*DD/32), dim3(32, 8)>>>(W2, w2th, w2tl, 2*DD, DD);

    // 1. embedding gather (+ bf16 split)
    {
        long total = (long)NTOK * (DD / 4);
        int blocks = (int)((total + 255) / 256);
        gather_kernel<<<blocks, 256>>>(seq, embed);
    }
    // 2. GEMM1: a1(hi/lo) = relu(h0 @ W1 + b1)   (M=32768, N=1024, K=512)
    mma_gemm_kernel<1><<<dim3(2*DD/128, NTOK/128), 256, GEMM_SMEM>>>(
        h0h, h0l, w1th, w1tl, b1, nullptr, a1h, a1l, NTOK, 2*DD, DD);
    // 3. GEMM2: ff = a1 @ W2 + b2                 (M=32768, N=512, K=1024)
    mma_gemm_kernel<0><<<dim3(DD/128, NTOK/128), 256, GEMM_SMEM>>>(
        a1h, a1l, w2th, w2tl, b2, ff, nullptr, nullptr, NTOK, DD, 2*DD);
    // 4. h = LN(h0 + ff), fused gate dots
    ln_kernel<<<NTOK, 256>>>(ln_g, ln_b, gW);
    // 5. windowed combine
    gatecomb_kernel<<<NTOK / 256, 256>>>(gb);
    // 6. top-256 per batch (radix select)
    topk_kernel<<<BB, 256>>>();
    // 7. q projection
    q_kernel<<<BB, 256>>>(qW, qb);
    // 8. attention read
    attn_kernel<<<BB, 256>>>();
    // 9. vocab projection
    out_kernel<<<(VV + 255) / 256, 256>>>(oW, ob, out);

    (void)in_sizes; (void)n_in; (void)out_size;
}

// round 14
// speedup vs baseline: 1.4539x; 1.4539x over previous
#include <cuda_runtime.h>
#include <cuda_bf16.h>
#include <math.h>
#include <stdint.h>

#define BB 8
#define TT 4096
#define DD 512
#define VV 50257
#define NSLOTS 256
#define KWIN 8
#define NTOK (BB*TT)          // 32768

// ---------------- scratch (device globals; no allocation) ----------------
__device__ __nv_bfloat16 g_h0h[(size_t)NTOK*DD];
__device__ __nv_bfloat16 g_h0l[(size_t)NTOK*DD];
__device__ __nv_bfloat16 g_a1h[(size_t)NTOK*2*DD];
__device__ __nv_bfloat16 g_a1l[(size_t)NTOK*2*DD];
__device__ float g_ff[(size_t)NTOK*DD];
__device__ float g_h [(size_t)NTOK*DD];
__device__ __nv_bfloat16 g_w1th[(size_t)2*DD*DD];
__device__ __nv_bfloat16 g_w1tl[(size_t)2*DD*DD];
__device__ __nv_bfloat16 g_w2th[(size_t)DD*2*DD];
__device__ __nv_bfloat16 g_w2tl[(size_t)DD*2*DD];
__device__ float g_u[NTOK];
__device__ float g_v[NTOK];
__device__ float g_gate[NTOK];
__device__ int   g_top[BB*NSLOTS];
__device__ float g_q[BB*DD];
__device__ float g_ctx[BB*DD];

// ======================= helpers =======================
__device__ __forceinline__ uint32_t smem_to_u32(const void* p) {
    uint32_t a;
    asm("{ .reg .u64 t; cvta.to.shared.u64 t, %1; cvt.u32.u64 %0, t; }" : "=r"(a) : "l"(p));
    return a;
}
__device__ __forceinline__ void bsplit(float x, __nv_bfloat16& h, __nv_bfloat16& l) {
    h = __float2bfloat16_rn(x);
    l = __float2bfloat16_rn(x - __bfloat162float(h));
}
__device__ __forceinline__ void ldm_x4(uint32_t& r0, uint32_t& r1, uint32_t& r2, uint32_t& r3,
                                       uint32_t addr) {
    asm volatile("ldmatrix.sync.aligned.m8n8.x4.shared.b16 {%0,%1,%2,%3}, [%4];"
        : "=r"(r0), "=r"(r1), "=r"(r2), "=r"(r3) : "r"(addr));
}
__device__ __forceinline__ void mma_bf16(float* c, const uint32_t* a, const uint32_t* b) {
    asm volatile("mma.sync.aligned.m16n8k16.row.col.f32.bf16.bf16.f32 "
        "{%0,%1,%2,%3}, {%4,%5,%6,%7}, {%8,%9}, {%0,%1,%2,%3};"
        : "+f"(c[0]), "+f"(c[1]), "+f"(c[2]), "+f"(c[3])
        : "r"(a[0]), "r"(a[1]), "r"(a[2]), "r"(a[3]), "r"(b[0]), "r"(b[1]));
}

// ---------------- weight transpose + bf16 split ----------------
__global__ void transpose_convert_kernel(const float* __restrict__ src,
                                         __nv_bfloat16* __restrict__ dh,
                                         __nv_bfloat16* __restrict__ dl,
                                         int R, int C) {
    __shared__ float t[32][33];
    int bx = blockIdx.x * 32, by = blockIdx.y * 32;
    int x = bx + threadIdx.x;
    #pragma unroll
    for (int j = 0; j < 32; j += 8) {
        int y = by + threadIdx.y + j;
        t[threadIdx.y + j][threadIdx.x] = src[(size_t)y * C + x];
    }
    __syncthreads();
    int xo = by + threadIdx.x;
    #pragma unroll
    for (int j = 0; j < 32; j += 8) {
        int yo = bx + threadIdx.y + j;
        float v = t[threadIdx.x][threadIdx.y + j];
        __nv_bfloat16 h, l; bsplit(v, h, l);
        dh[(size_t)yo * R + xo] = h;
        dl[(size_t)yo * R + xo] = l;
    }
}

// ---------------- embedding gather + bf16 split ----------------
__global__ void gather_kernel(const int* __restrict__ seq,
                              const float* __restrict__ embed) {
    long i = (long)blockIdx.x * blockDim.x + threadIdx.x;
    long total = (long)NTOK * (DD/4);
    if (i >= total) return;
    int tokpos = (int)(i >> 7);
    int dc     = (int)(i & 127);
    int tok = seq[tokpos];
    float4 e = ((const float4*)embed)[(long)tok * 128 + dc];
    __nv_bfloat16 hx, lx, hy, ly, hz, lz, hw, lw;
    bsplit(e.x, hx, lx); bsplit(e.y, hy, ly);
    bsplit(e.z, hz, lz); bsplit(e.w, hw, lw);
    __nv_bfloat162* ph = (__nv_bfloat162*)g_h0h + i * 2;
    __nv_bfloat162* pl = (__nv_bfloat162*)g_h0l + i * 2;
    ph[0] = __nv_bfloat162{hx, hy}; ph[1] = __nv_bfloat162{hz, hw};
    pl[0] = __nv_bfloat162{lx, ly}; pl[1] = __nv_bfloat162{lz, lw};
}

// ============== mma.sync bf16 3-pass split GEMM (R6 exact: best measured) ==============
// C = act(A @ Bt^T + bias); A [M][K], Bt [N][K] (both bf16 hi/lo, K-major)
// CTA tile 128x128, 8 warps (2m x 4n), warp tile 64x32, K-chunk 16,
// register-staged double buffer (LDG->reg->STS).
#define SPITCH 24                       // bf16 elems per smem row (48B)
#define STILE  (128 * SPITCH * 2)       // 6144 bytes per tile
#define GEMM_SMEM (8 * STILE)           // 49152

template<int EPI>
__global__ void __launch_bounds__(256)
mma_gemm_kernel(const __nv_bfloat16* __restrict__ Ah, const __nv_bfloat16* __restrict__ Al,
                const __nv_bfloat16* __restrict__ Bh, const __nv_bfloat16* __restrict__ Bl,
                const float* __restrict__ bias,
                float* __restrict__ Cf,
                __nv_bfloat16* __restrict__ Ch, __nv_bfloat16* __restrict__ Cl,
                int M, int N, int K) {
    extern __shared__ char smem[];
    uint32_t sb = smem_to_u32(smem);
    int tid = threadIdx.x;
    int lane = tid & 31, wid = tid >> 5;
    int wm = wid >> 2, wn = wid & 3;            // 2 x 4 warp grid
    int bx = blockIdx.x, by = blockIdx.y;

    // global load mapping: 256 threads, each 16B per array per chunk
    int grow = tid >> 1;                        // 0..127
    int ghalf = tid & 1;                        // 0..1
    const __nv_bfloat16* pAh = Ah + (size_t)(by * 128 + grow) * K + ghalf * 8;
    const __nv_bfloat16* pAl = Al + (size_t)(by * 128 + grow) * K + ghalf * 8;
    const __nv_bfloat16* pBh = Bh + (size_t)(bx * 128 + grow) * K + ghalf * 8;
    const __nv_bfloat16* pBl = Bl + (size_t)(bx * 128 + grow) * K + ghalf * 8;
    uint32_t sdst = (uint32_t)(grow * 48 + ghalf * 16);

    #define TBASE(arr, buf) ((uint32_t)((arr) * 2 * STILE + (buf) * STILE))

    float acc[4][4][4];
    #pragma unroll
    for (int i = 0; i < 4; i++)
        #pragma unroll
        for (int j = 0; j < 4; j++)
            #pragma unroll
            for (int r = 0; r < 4; r++) acc[i][j][r] = 0.f;

    uint32_t a_off = (uint32_t)((wm * 64 + (lane & 15)) * 48 + (lane >> 4) * 16);
    uint32_t b_off = (uint32_t)((wn * 32 + (lane & 7) + ((lane >> 4) << 3)) * 48
                                + ((lane >> 3) & 1) * 16);

    int nk = K >> 4;
    // preload chunk 0 into buf 0
    {
        *(uint4*)(smem + TBASE(0,0) + sdst) = *(const uint4*)(pAh);
        *(uint4*)(smem + TBASE(1,0) + sdst) = *(const uint4*)(pAl);
        *(uint4*)(smem + TBASE(2,0) + sdst) = *(const uint4*)(pBh);
        *(uint4*)(smem + TBASE(3,0) + sdst) = *(const uint4*)(pBl);
    }
    __syncthreads();

    for (int c = 0; c < nk; c++) {
        int buf = c & 1;
        uint4 vAh, vAl, vBh, vBl;
        if (c + 1 < nk) {
            int ko = (c + 1) * 16;
            vAh = *(const uint4*)(pAh + ko);
            vAl = *(const uint4*)(pAl + ko);
            vBh = *(const uint4*)(pBh + ko);
            vBl = *(const uint4*)(pBl + ko);
        }
        uint32_t sA_h = sb + TBASE(0, buf), sA_l = sb + TBASE(1, buf);
        uint32_t sB_h = sb + TBASE(2, buf), sB_l = sb + TBASE(3, buf);

        uint32_t a[4][4], b[4][2];
        // ---- pass hh: A_hi x B_hi ----
        #pragma unroll
        for (int mt = 0; mt < 4; mt++)
            ldm_x4(a[mt][0], a[mt][1], a[mt][2], a[mt][3], sA_h + a_off + mt * 768);
        #pragma unroll
        for (int p = 0; p < 2; p++)
            ldm_x4(b[2*p][0], b[2*p][1], b[2*p+1][0], b[2*p+1][1], sB_h + b_off + p * 768);
        #pragma unroll
        for (int mt = 0; mt < 4; mt++)
            #pragma unroll
            for (int nt = 0; nt < 4; nt++) mma_bf16(acc[mt][nt], a[mt], b[nt]);
        // ---- pass hl: A_hi x B_lo ----
        #pragma unroll
        for (int p = 0; p < 2; p++)
            ldm_x4(b[2*p][0], b[2*p][1], b[2*p+1][0], b[2*p+1][1], sB_l + b_off + p * 768);
        #pragma unroll
        for (int mt = 0; mt < 4; mt++)
            #pragma unroll
            for (int nt = 0; nt < 4; nt++) mma_bf16(acc[mt][nt], a[mt], b[nt]);
        // ---- pass lh: A_lo x B_hi ----
        #pragma unroll
        for (int mt = 0; mt < 4; mt++)
            ldm_x4(a[mt][0], a[mt][1], a[mt][2], a[mt][3], sA_l + a_off + mt * 768);
        #pragma unroll
        for (int p = 0; p < 2; p++)
            ldm_x4(b[2*p][0], b[2*p][1], b[2*p+1][0], b[2*p+1][1], sB_h + b_off + p * 768);
        #pragma unroll
        for (int mt = 0; mt < 4; mt++)
            #pragma unroll
            for (int nt = 0; nt < 4; nt++) mma_bf16(acc[mt][nt], a[mt], b[nt]);

        if (c + 1 < nk) {
            int nb = buf ^ 1;
            *(uint4*)(smem + TBASE(0,nb) + sdst) = vAh;
            *(uint4*)(smem + TBASE(1,nb) + sdst) = vAl;
            *(uint4*)(smem + TBASE(2,nb) + sdst) = vBh;
            *(uint4*)(smem + TBASE(3,nb) + sdst) = vBl;
        }
        __syncthreads();
    }

    // ---- epilogue ----
    int m_base = by * 128 + wm * 64;
    int n_base = bx * 128 + wn * 32;
    #pragma unroll
    for (int mt = 0; mt < 4; mt++) {
        #pragma unroll
        for (int nt = 0; nt < 4; nt++) {
            int n0 = n_base + nt * 8 + (lane & 3) * 2;
            float bs0 = bias[n0], bs1 = bias[n0 + 1];
            #pragma unroll
            for (int half = 0; half < 2; half++) {
                int m = m_base + mt * 16 + (lane >> 2) + half * 8;
                float v0 = acc[mt][nt][half * 2 + 0] + bs0;
                float v1 = acc[mt][nt][half * 2 + 1] + bs1;
                if (EPI) {
                    v0 = fmaxf(v0, 0.f); v1 = fmaxf(v1, 0.f);
                    __nv_bfloat16 h0b, l0b, h1b, l1b;
                    bsplit(v0, h0b, l0b); bsplit(v1, h1b, l1b);
                    *(__nv_bfloat162*)(Ch + (size_t)m * N + n0) = __nv_bfloat162{h0b, h1b};
                    *(__nv_bfloat162*)(Cl + (size_t)m * N + n0) = __nv_bfloat162{l0b, l1b};
                } else {
                    *(float2*)(Cf + (size_t)m * N + n0) = float2{v0, v1};
                }
            }
        }
    }
    #undef TBASE
}

// ---------------- block reduce helper ----------------
__device__ __forceinline__ float block_reduce_sum(float v, float* red) {
    int tid = threadIdx.x;
    #pragma unroll
    for (int o = 16; o > 0; o >>= 1) v += __shfl_down_sync(0xffffffffu, v, o);
    if ((tid & 31) == 0) red[tid >> 5] = v;
    __syncthreads();
    int nw = blockDim.x >> 5;
    if (tid < 32) {
        float x = (tid < nw) ? red[tid] : 0.f;
        #pragma unroll
        for (int o = 16; o > 0; o >>= 1) x += __shfl_down_sync(0xffffffffu, x, o);
        if (tid == 0) red[0] = x;
    }
    __syncthreads();
    float r = red[0];
    __syncthreads();
    return r;
}

// ---------------- fused layernorm(h0 + ff) + gate dots ----------------
__global__ void __launch_bounds__(256)
ln_kernel(const float* __restrict__ g, const float* __restrict__ b,
          const float* __restrict__ gW) {
    __shared__ float red[32];
    int row = blockIdx.x;
    int tid = threadIdx.x;
    long base = (long)row * DD;
    float x1 = __bfloat162float(g_h0h[base + tid]) + __bfloat162float(g_h0l[base + tid])
             + g_ff[base + tid];
    float x2 = __bfloat162float(g_h0h[base + tid + 256]) + __bfloat162float(g_h0l[base + tid + 256])
             + g_ff[base + tid + 256];
    float mean = block_reduce_sum(x1 + x2, red) * (1.f / DD);
    float d1 = x1 - mean, d2 = x2 - mean;
    float var = block_reduce_sum(d1*d1 + d2*d2, red) * (1.f / DD);
    float rstd = rsqrtf(var + 1e-5f);
    float h1 = d1 * rstd * g[tid]       + b[tid];
    float h2 = d2 * rstd * g[tid + 256] + b[tid + 256];
    g_h[base + tid]       = h1;
    g_h[base + tid + 256] = h2;
    float su = h1 * gW[tid]      + h2 * gW[tid + 256];
    float sv = h1 * gW[DD + tid] + h2 * gW[DD + tid + 256];
    su = block_reduce_sum(su, red);
    sv = block_reduce_sum(sv, red);
    if (tid == 0) { g_u[row] = su; g_v[row] = sv; }
}

// ---------------- gate = sigmoid(u + windowed-mean(v) + gb) ----------------
__global__ void gatecomb_kernel(const float* __restrict__ gb) {
    int i = blockIdx.x * blockDim.x + threadIdx.x;
    if (i >= NTOK) return;
    int t = i % TT;
    int bstart = i - t;
    int s = min(t + 1, TT);
    int e = min(t + 1 + KWIN, TT);
    int cnt = e - s;
    float fsum = 0.f;
    for (int j = s; j < e; j++) fsum += g_v[bstart + j];
    float fut = (cnt > 0) ? fsum / (float)cnt : 0.f;
    float logit = g_u[i] + fut + gb[0];
    g_gate[i] = 1.f / (1.f + expf(-logit));
}

// ---------------- top-256 per batch via 4-pass radix select ----------------
__global__ void __launch_bounds__(256)
topk_kernel() {
    __shared__ uint32_t keys[TT];        // 16 KB
    __shared__ int hist[256];
    __shared__ int wsg[8], wse[8];
    __shared__ uint32_t sh_prefix;
    __shared__ int sh_need, sh_gbase, sh_ebase;
    int b = blockIdx.x, tid = threadIdx.x;
    int lane = tid & 31, wid = tid >> 5;

    for (int i = tid; i < TT; i += 256) {
        uint32_t u = __float_as_uint(g_gate[b * TT + i]);
        u = (u & 0x80000000u) ? ~u : (u | 0x80000000u);
        keys[i] = u;
    }
    if (tid == 0) { sh_prefix = 0; sh_need = NSLOTS; sh_gbase = 0; sh_ebase = 0; }
    __syncthreads();

    for (int p = 3; p >= 0; p--) {
        hist[tid] = 0;
        __syncthreads();
        uint32_t pmask = (p == 3) ? 0u : (0xFFFFFFFFu << ((p + 1) * 8));
        uint32_t prefix = sh_prefix;
        int shift = p * 8;
        for (int i = tid; i < TT; i += 256) {
            uint32_t k = keys[i];
            if ((k & pmask) == prefix)
                atomicAdd(&hist[(k >> shift) & 0xFF], 1);
        }
        __syncthreads();
        if (tid == 0) {
            int need = sh_need, acc = 0, t = 255;
            for (; t > 0; t--) {
                if (acc + hist[t] >= need) break;
                acc += hist[t];
            }
            sh_need = need - acc;
            sh_prefix = prefix | ((uint32_t)t << shift);
        }
        __syncthreads();
    }
    uint32_t T = sh_prefix;
    int need = sh_need;

    for (int base = 0; base < TT; base += 256) {
        uint32_t k = keys[base + tid];
        bool sg = (k > T);
        bool se = (k == T);
        unsigned bg = __ballot_sync(0xffffffffu, sg);
        unsigned be = __ballot_sync(0xffffffffu, se);
        if (lane == 0) { wsg[wid] = __popc(bg); wse[wid] = __popc(be); }
        __syncthreads();
        int wog = 0, woe = 0;
        for (int w = 0; w < wid; w++) { wog += wsg[w]; woe += wse[w]; }
        unsigned lmask = (1u << lane) - 1;
        if (sg) {
            int rg = sh_gbase + wog + __popc(bg & lmask);
            g_top[b * NSLOTS + rg] = base + tid;
        }
        if (se) {
            int re = sh_ebase + woe + __popc(be & lmask);
            if (re < need)
                g_top[b * NSLOTS + (NSLOTS - need) + re] = base + tid;
        }
        __syncthreads();
        if (tid == 0) {
            int tg = 0, te = 0;
            for (int w = 0; w < 8; w++) { tg += wsg[w]; te += wse[w]; }
            sh_gbase += tg; sh_ebase += te;
        }
        __syncthreads();
    }
}

// ---------------- q = h[:, -1, :] @ q_W + q_b ----------------
__global__ void __launch_bounds__(256)
q_kernel(const float* __restrict__ qW, const float* __restrict__ qb) {
    __shared__ float hl[DD];
    int b = blockIdx.x;
    int tid = threadIdx.x;
    long base = ((long)b * TT + (TT - 1)) * DD;
    for (int d = tid; d < DD; d += 256) hl[d] = g_h[base + d];
    __syncthreads();
    for (int j = tid; j < DD; j += 256) {
        float s = qb[j];
        for (int d = 0; d < DD; d++) s += hl[d] * qW[(long)d * DD + j];
        g_q[b * DD + j] = s;
    }
}

// ---------------- scores -> softmax -> ctx ----------------
__global__ void __launch_bounds__(256)
attn_kernel() {
    __shared__ float qs[DD];
    __shared__ float sc[NSLOTS];
    __shared__ int   rows[NSLOTS];
    __shared__ float red[32];
    int b = blockIdx.x;
    int tid = threadIdx.x;
    int wid = tid >> 5, lane = tid & 31;
    for (int d = tid; d < DD; d += 256) qs[d] = g_q[b * DD + d];
    for (int m = tid; m < NSLOTS; m += 256) rows[m] = b * TT + g_top[b * NSLOTS + m];
    __syncthreads();
    for (int m = wid; m < NSLOTS; m += 8) {
        long base = (long)rows[m] * DD;
        float s = 0.f;
        for (int d = lane; d < DD; d += 32) s += g_h[base + d] * qs[d];
        #pragma unroll
        for (int o = 16; o > 0; o >>= 1) s += __shfl_down_sync(0xffffffffu, s, o);
        if (lane == 0) sc[m] = s;
    }
    __syncthreads();
    float v = (tid < NSLOTS) ? sc[tid] : -1e30f;
    float vm = v;
    #pragma unroll
    for (int o = 16; o > 0; o >>= 1) vm = fmaxf(vm, __shfl_down_sync(0xffffffffu, vm, o));
    if ((tid & 31) == 0) red[tid >> 5] = vm;
    __syncthreads();
    if (tid < 32) {
        float x = (tid < 8) ? red[tid] : -1e30f;
        #pragma unroll
        for (int o = 16; o > 0; o >>= 1) x = fmaxf(x, __shfl_down_sync(0xffffffffu, x, o));
        if (tid == 0) red[0] = x;
    }
    __syncthreads();
    float mx = red[0];
    __syncthreads();
    float e = (tid < NSLOTS) ? expf(v - mx) : 0.f;
    float tot = block_reduce_sum(e, red);
    if (tid < NSLOTS) sc[tid] = e / tot;
    __syncthreads();
    for (int d = tid; d < DD; d += 256) {
        float s = 0.f;
        for (int m = 0; m < NSLOTS; m++)
            s += sc[m] * g_h[(long)rows[m] * DD + d];
        g_ctx[b * DD + d] = s;
    }
}

// ---------------- out = ctx @ out_W + out_b ----------------
__global__ void __launch_bounds__(256)
out_kernel(const float* __restrict__ oW, const float* __restrict__ ob,
           float* __restrict__ out) {
    __shared__ float cs[BB * DD];
    int tid = threadIdx.x;
    for (int i = tid; i < BB * DD; i += 256) cs[i] = g_ctx[i];
    __syncthreads();
    int v = blockIdx.x * 256 + tid;
    if (v >= VV) return;
    float acc[BB];
    #pragma unroll
    for (int b = 0; b < BB; b++) acc[b] = 0.f;
    for (int d = 0; d < DD; d++) {
        float w = oW[(long)d * VV + v];
        #pragma unroll
        for (int b = 0; b < BB; b++) acc[b] += cs[b * DD + d] * w;
    }
    float bias = ob[v];
    #pragma unroll
    for (int b = 0; b < BB; b++) out[(long)b * VV + v] = acc[b] + bias;
}

// ---------------- launch ----------------
extern "C" void kernel_launch(void* const* d_in, const int* in_sizes, int n_in,
                              void* d_out, int out_size) {
    const int*   seq   = (const int*)  d_in[0];
    const float* embed = (const float*)d_in[1];
    const float* W1    = (const float*)d_in[2];
    const float* b1    = (const float*)d_in[3];
    const float* W2    = (const float*)d_in[4];
    const float* b2    = (const float*)d_in[5];
    const float* ln_g  = (const float*)d_in[6];
    const float* ln_b  = (const float*)d_in[7];
    const float* gW    = (const float*)d_in[8];
    const float* gb    = (const float*)d_in[9];
    const float* qW    = (const float*)d_in[10];
    const float* qb    = (const float*)d_in[11];
    const float* oW    = (const float*)d_in[12];
    const float* ob    = (const float*)d_in[13];
    float* out = (float*)d_out;

    __nv_bfloat16 *h0h, *h0l, *a1h, *a1l, *w1th, *w1tl, *w2th, *w2tl;
    float *ff;
    cudaGetSymbolAddress((void**)&h0h,  g_h0h);
    cudaGetSymbolAddress((void**)&h0l,  g_h0l);
    cudaGetSymbolAddress((void**)&a1h,  g_a1h);
    cudaGetSymbolAddress((void**)&a1l,  g_a1l);
    cudaGetSymbolAddress((void**)&w1th, g_w1th);
    cudaGetSymbolAddress((void**)&w1tl, g_w1tl);
    cudaGetSymbolAddress((void**)&w2th, g_w2th);
    cudaGetSymbolAddress((void**)&w2tl, g_w2tl);
    cudaGetSymbolAddress((void**)&ff,   g_ff);

    cudaFuncSetAttribute(mma_gemm_kernel<1>,
                         cudaFuncAttributeMaxDynamicSharedMemorySize, GEMM_SMEM);
    cudaFuncSetAttribute(mma_gemm_kernel<0>,
                         cudaFuncAttributeMaxDynamicSharedMemorySize, GEMM_SMEM);

    // 0. weight transpose + split
    transpose_convert_kernel<<<dim3(2*DD/32, DD/32), dim3(32, 8)>>>(W1, w1th, w1tl, DD, 2*DD);
    transpose_convert_kernel<<<dim3(DD/32, 2*DD/32), dim3(32, 8)>>>(W2, w2th, w2tl, 2*DD, DD);

    // 1. embedding gather (+ bf16 split)
    {
        long total = (long)NTOK * (DD / 4);
        int blocks = (int)((total + 255) / 256);
        gather_kernel<<<blocks, 256>>>(seq, embed);
    }
    // 2. GEMM1: a1(hi/lo) = relu(h0 @ W1 + b1)   (M=32768, N=1024, K=512)
    mma_gemm_kernel<1><<<dim3(2*DD/128, NTOK/128), 256, GEMM_SMEM>>>(
        h0h, h0l, w1th, w1tl, b1, nullptr, a1h, a1l, NTOK, 2*DD, DD);
    // 3. GEMM2: ff = a1 @ W2 + b2                 (M=32768, N=512, K=1024)
    mma_gemm_kernel<0><<<dim3(DD/128, NTOK/128), 256, GEMM_SMEM>>>(
        a1h, a1l, w2th, w2tl, b2, ff, nullptr, nullptr, NTOK, DD, 2*DD);
    // 4. h = LN(h0 + ff), fused gate dots
    ln_kernel<<<NTOK, 256>>>(ln_g, ln_b, gW);
    // 5. windowed combine
    gatecomb_kernel<<<NTOK / 256, 256>>>(gb);
    // 6. top-256 per batch (radix select)
    topk_kernel<<<BB, 256>>>();
    // 7. q projection
    q_kernel<<<BB, 256>>>(qW, qb);
    // 8. attention read
    attn_kernel<<<BB, 256>>>();
    // 9. vocab projection
    out_kernel<<<(VV + 255) / 256, 256>>>(oW, ob, out);

    (void)in_sizes; (void)n_in; (void)out_size;
}